// round 6
// baseline (speedup 1.0000x reference)
#include <cuda_runtime.h>

// ---------------- problem constants ----------------
#define NN    20000
#define EE    240000
#define ETOT  (EE + NN)        // edges + self loops = 260000
#define GG    64
#define FF    768
#define H1c   128
#define PEc   32
#define DDc   160              // H1 + PE
#define NHEAD 5
#define HCc   800              // NHEAD * DDc
#define H2c   128
#define OUTc  16
#define NEG_SLOPE 0.2f

// ---------------- device scratch (static, no allocs) ----------------
__device__ float d_h   [NN * DDc];
__device__ float d_xl  [NN * HCc];
__device__ float d_xr  [NN * HCc];
__device__ float d_g1  [NN * HCc];
__device__ float d_hg  [NN * HCc];
__device__ float d_g2  [NN * HCc];
__device__ float d_dinv[NN];
__device__ int   d_cnt [NN];
__device__ int   d_rowptr[NN + 1];
__device__ int   d_csrc[ETOT];
__device__ int   d_gstart[GG + 1];
__device__ float d_pool[GG * 2 * HCc];

// ---------------- CSR build ----------------
__global__ void k_zero_cnt() {
    int i = blockIdx.x * blockDim.x + threadIdx.x;
    if (i < NN) d_cnt[i] = 0;
}

__global__ void k_count(const int* __restrict__ ei) {
    int e = blockIdx.x * blockDim.x + threadIdx.x;
    if (e >= ETOT) return;
    int dst = (e < EE) ? ei[EE + e] : (e - EE);
    atomicAdd(&d_cnt[dst], 1);
}

__global__ void k_scan() {
    __shared__ int sh[1024];
    __shared__ int soff;
    int t = threadIdx.x;
    if (t == 0) soff = 0;
    __syncthreads();
    for (int base = 0; base < NN; base += 1024) {
        int i = base + t;
        int v = (i < NN) ? d_cnt[i] : 0;
        if (i < NN) {
            d_dinv[i] = rsqrtf((float)v);   // deg >= 1 (self loop)
            d_cnt[i] = 0;
        }
        sh[t] = v;
        __syncthreads();
        for (int off = 1; off < 1024; off <<= 1) {
            int add = (t >= off) ? sh[t - off] : 0;
            __syncthreads();
            sh[t] += add;
            __syncthreads();
        }
        if (i < NN) d_rowptr[i] = soff + sh[t] - v;
        __syncthreads();
        if (t == 1023) soff += sh[1023];
        __syncthreads();
    }
    if (t == 0) d_rowptr[NN] = soff;
}

__global__ void k_fill(const int* __restrict__ ei) {
    int e = blockIdx.x * blockDim.x + threadIdx.x;
    if (e >= ETOT) return;
    int src, dst;
    if (e < EE) { src = ei[e]; dst = ei[EE + e]; }
    else        { src = e - EE; dst = e - EE; }
    int pos = d_rowptr[dst] + atomicAdd(&d_cnt[dst], 1);
    d_csrc[pos] = src;
}

// ---------------- TF32 tensor-core GEMM, 128x128 CTA, 4 warps, 64x64 warp tile ----
// Packed-fragment smem: one LDS.64 per mma fragment, conflict-free.
// Requires K % 32 == 0; lda,ldb,ldc multiples of 4; Nc multiple of 4.
#define A_STR2 20                 // float2 per A m-row (16 + 4 pad)
#define B_STR2 132                // float2 per B (ks,kq)-row (128 + 4 pad)
#define A_F2   (128 * A_STR2)    // 2560 float2
#define B_F2   (16 * B_STR2)     // 2112 float2

__device__ __forceinline__ float to_tf32(float x) {
    float r;
    asm("cvt.rna.tf32.f32 %0, %1;" : "=f"(r) : "f"(x));
    return r;
}

__device__ __forceinline__ void mma_tf32(float c[4], float a0, float a1, float a2, float a3,
                                         float b0, float b1) {
    asm volatile(
        "mma.sync.aligned.m16n8k8.row.col.f32.tf32.tf32.f32 "
        "{%0,%1,%2,%3}, {%4,%5,%6,%7}, {%8,%9}, {%0,%1,%2,%3};\n"
        : "+f"(c[0]), "+f"(c[1]), "+f"(c[2]), "+f"(c[3])
        : "r"(__float_as_uint(a0)), "r"(__float_as_uint(a1)),
          "r"(__float_as_uint(a2)), "r"(__float_as_uint(a3)),
          "r"(__float_as_uint(b0)), "r"(__float_as_uint(b1)));
}

__global__ void __launch_bounds__(128)
k_gemm_tf32(const float* __restrict__ A, const float* __restrict__ B,
            const float* __restrict__ bias, float* __restrict__ C,
            int M, int Nc, int K, int lda, int ldb, int ldc, int relu)
{
    // packed A: pair (k, k+4): Af[(m*A_STR2 + ks*4 + kq)*2 + e]
    // packed B: pair (k, k+4): Bf[((ks*4+kq)*B_STR2 + n)*2 + e]
    __shared__ float Af[2 * A_F2];
    __shared__ float Bf[2 * B_F2];

    const int t    = threadIdx.x;
    const int lane = t & 31;
    const int warp = t >> 5;
    const int wm   = warp >> 1;         // 0..1 -> m offset wm*64
    const int wn   = warp & 1;          // 0..1 -> n offset wn*64
    const int g    = lane >> 2;
    const int kq   = lane & 3;

    const int m0 = blockIdx.y * 128, n0 = blockIdx.x * 128;
    const float4 z4 = make_float4(0.f, 0.f, 0.f, 0.f);

    // loader maps
    const int acol  = t & 7;           // k-quad 0..7
    const int abase = t >> 3;          // row base 0..15 (+16p)
    const int aks   = acol >> 1, ae = acol & 1;
    const int bcol  = t & 31;          // n-quad 0..31
    const int bbase = t >> 5;          // k base 0..3 (+4p)

    float acc[4][8][4];
    #pragma unroll
    for (int i = 0; i < 4; i++)
        #pragma unroll
        for (int j = 0; j < 8; j++)
            #pragma unroll
            for (int q = 0; q < 4; q++) acc[i][j][q] = 0.f;

    const int nk = K >> 5;
    for (int kt = 0; kt < nk; kt++) {
        const int kb = kt << 5;
        __syncthreads();
        // ---- fill A (128 rows x 32 k) ----
        #pragma unroll
        for (int p = 0; p < 8; p++) {
            int row = abase + p * 16;
            int gm = m0 + row;
            float4 r = (gm < M) ? *(const float4*)&A[(size_t)gm * lda + kb + acol * 4] : z4;
            float* dst = Af + (row * A_STR2 + aks * 4) * 2 + ae;
            dst[0] = to_tf32(r.x); dst[2] = to_tf32(r.y);
            dst[4] = to_tf32(r.z); dst[6] = to_tf32(r.w);
        }
        // ---- fill B (32 k x 128 n) ----
        #pragma unroll
        for (int p = 0; p < 8; p++) {
            int row = bbase + p * 4;            // k within tile
            int gn = n0 + bcol * 4;
            float4 r = (gn < Nc) ? *(const float4*)&B[(size_t)(kb + row) * ldb + gn] : z4;
            int ks = row >> 3, kq4 = row & 7;
            int kqq = kq4 & 3, e = kq4 >> 2;
            float* dst = Bf + ((ks * 4 + kqq) * B_STR2 + bcol * 4) * 2 + e;
            dst[0] = to_tf32(r.x); dst[2] = to_tf32(r.y);
            dst[4] = to_tf32(r.z); dst[6] = to_tf32(r.w);
        }
        __syncthreads();

        // ---- compute 4 ks steps ----
        #pragma unroll
        for (int ks = 0; ks < 4; ks++) {
            float2 pa[4][2];
            #pragma unroll
            for (int mi = 0; mi < 4; mi++) {
                int mr = wm * 64 + mi * 16;
                pa[mi][0] = *(const float2*)&Af[((mr + g)     * A_STR2 + ks * 4 + kq) * 2];
                pa[mi][1] = *(const float2*)&Af[((mr + 8 + g) * A_STR2 + ks * 4 + kq) * 2];
            }
            float2 pb[8];
            #pragma unroll
            for (int ni = 0; ni < 8; ni++) {
                int nc = wn * 64 + ni * 8 + g;
                pb[ni] = *(const float2*)&Bf[((ks * 4 + kq) * B_STR2 + nc) * 2];
            }
            #pragma unroll
            for (int mi = 0; mi < 4; mi++)
                #pragma unroll
                for (int ni = 0; ni < 8; ni++)
                    mma_tf32(acc[mi][ni], pa[mi][0].x, pa[mi][1].x, pa[mi][0].y, pa[mi][1].y,
                             pb[ni].x, pb[ni].y);
        }
    }

    // ---- epilogue ----
    #pragma unroll
    for (int mi = 0; mi < 4; mi++) {
        #pragma unroll
        for (int half = 0; half < 2; half++) {
            int gm = m0 + wm * 64 + mi * 16 + g + half * 8;
            if (gm >= M) continue;
            #pragma unroll
            for (int ni = 0; ni < 8; ni++) {
                int gn = n0 + wn * 64 + ni * 8 + 2 * kq;
                if (gn >= Nc) continue;
                float v0 = acc[mi][ni][half * 2 + 0];
                float v1 = acc[mi][ni][half * 2 + 1];
                if (bias) { v0 += bias[gn]; v1 += bias[gn + 1]; }
                if (relu) { v0 = fmaxf(v0, 0.f); v1 = fmaxf(v1, 0.f); }
                float2 st; st.x = v0; st.y = v1;
                *(float2*)&C[(size_t)gm * ldc + gn] = st;
            }
        }
    }
}

// copy pe_enc into h[:, 128:160]
__global__ void k_pe(const float* __restrict__ pe) {
    int i = blockIdx.x * blockDim.x + threadIdx.x;
    if (i >= NN * PEc) return;
    int n = i / PEc, c = i % PEc;
    d_h[n * DDc + H1c + c] = pe[i];
}

// ---------------- fused GATv2: score + online softmax + aggregation ----------------
__global__ void __launch_bounds__(128)
k_gat_fused(const float* __restrict__ att, const float* __restrict__ gat_bias) {
    __shared__ float s_att[HCc];
    const int t = threadIdx.x;
    for (int k = t; k < HCc; k += 128) s_att[k] = att[k];
    __syncthreads();

    const int n = (blockIdx.x * 128 + t) >> 5;
    const int lane = t & 31;
    if (n >= NN) return;

    float xrr[25];
    {
        const float* xr = d_xr + (size_t)n * HCc;
        #pragma unroll
        for (int j = 0; j < 25; j++) xrr[j] = xr[lane + 32 * j];
    }

    float m[NHEAD], s[NHEAD], acc[25];
    #pragma unroll
    for (int h = 0; h < NHEAD; h++) { m[h] = -1e30f; s[h] = 0.f; }
    #pragma unroll
    for (int j = 0; j < 25; j++) acc[j] = 0.f;

    const int beg = d_rowptr[n], end = d_rowptr[n + 1];
    for (int i = beg; i < end; i++) {
        const int src = d_csrc[i];
        const float* xl = d_xl + (size_t)src * HCc;
        float xlr[25];
        #pragma unroll
        for (int j = 0; j < 25; j++) xlr[j] = xl[lane + 32 * j];

        float sc[NHEAD];
        #pragma unroll
        for (int h = 0; h < NHEAD; h++) {
            float p = 0.f;
            #pragma unroll
            for (int k5 = 0; k5 < 5; k5++) {
                int j = h * 5 + k5;
                float mm = xlr[j] + xrr[j];
                mm = (mm > 0.f) ? mm : NEG_SLOPE * mm;
                p += mm * s_att[lane + 32 * j];
            }
            #pragma unroll
            for (int off = 16; off > 0; off >>= 1)
                p += __shfl_xor_sync(0xffffffffu, p, off);
            sc[h] = p;
        }

        float scl[NHEAD], w[NHEAD];
        #pragma unroll
        for (int h = 0; h < NHEAD; h++) {
            float nm = fmaxf(m[h], sc[h]);
            scl[h] = __expf(m[h] - nm);
            w[h]   = __expf(sc[h] - nm);
            s[h] = s[h] * scl[h] + w[h];
            m[h] = nm;
        }
        #pragma unroll
        for (int j = 0; j < 25; j++) {
            const int h = j / 5;
            acc[j] = acc[j] * scl[h] + w[h] * xlr[j];
        }
    }

    float rs[NHEAD];
    #pragma unroll
    for (int h = 0; h < NHEAD; h++) rs[h] = 1.f / s[h];
    float* g1 = d_g1 + (size_t)n * HCc;
    #pragma unroll
    for (int j = 0; j < 25; j++) {
        int c = lane + 32 * j;
        g1[c] = fmaxf(acc[j] * rs[j / 5] + gat_bias[c], 0.f);
    }
}

// ---------------- GCN aggregation, gather form, float4 (one warp / dst node) -------
__global__ void k_gcn_agg(const float* __restrict__ b_gcn) {
    int n = (blockIdx.x * blockDim.x + threadIdx.x) >> 5;
    int lane = threadIdx.x & 31;
    if (n >= NN) return;
    float4 a[6];
    float atail = 0.f;
    #pragma unroll
    for (int q = 0; q < 6; q++) a[q] = make_float4(0.f, 0.f, 0.f, 0.f);
    int beg = d_rowptr[n], end = d_rowptr[n + 1];
    float dn = d_dinv[n];
    for (int i = beg; i < end; i++) {
        int src = d_csrc[i];
        float w = d_dinv[src] * dn;
        const float4* hg = (const float4*)(d_hg + (size_t)src * HCc);
        #pragma unroll
        for (int q = 0; q < 6; q++) {
            float4 v = hg[lane + 32 * q];
            a[q].x += w * v.x; a[q].y += w * v.y;
            a[q].z += w * v.z; a[q].w += w * v.w;
        }
        if (lane < 8) atail += w * ((const float*)hg)[768 + lane + 24 * (lane >= 8 ? 0 : 0)];
    }
    // NOTE: tail covers channels 768..799 = 8 float4 = 32 floats; lane<8 handles float4
    // redo tail as float4 for lanes 0..7:
    float* g2 = d_g2 + (size_t)n * HCc;
    #pragma unroll
    for (int q = 0; q < 6; q++) {
        int c = (lane + 32 * q) * 4;
        float4 b = *(const float4*)&b_gcn[c];
        float4 o;
        o.x = fmaxf(a[q].x + b.x, 0.f); o.y = fmaxf(a[q].y + b.y, 0.f);
        o.z = fmaxf(a[q].z + b.z, 0.f); o.w = fmaxf(a[q].w + b.w, 0.f);
        *(float4*)&g2[c] = o;
    }
    // tail channels 768..799 handled separately below (scalar, lane-based)
    {
        float accT = 0.f;
        int c = 768 + lane;
        if (c < HCc) {
            for (int i = beg; i < end; i++) {
                int src = d_csrc[i];
                float w = d_dinv[src] * dn;
                accT += w * d_hg[(size_t)src * HCc + c];
            }
            g2[c] = fmaxf(accT + b_gcn[c], 0.f);
        }
    }
    (void)atail;
}

// ---------------- graph boundaries (batch sorted) ----------------
__global__ void k_gstart(const int* __restrict__ batch) {
    int g = threadIdx.x;
    if (g > GG) return;
    int lo = 0, hi = NN;
    while (lo < hi) {
        int mid = (lo + hi) >> 1;
        if (batch[mid] < g) lo = mid + 1; else hi = mid;
    }
    d_gstart[g] = lo;
}

// ---------------- pooling: weighted mean + max per graph (float4) ----------------
__global__ void __launch_bounds__(256) k_pool(const float* __restrict__ fw) {
    int g = blockIdx.x;
    int t = threadIdx.x;
    int s = d_gstart[g], e2 = d_gstart[g + 1];
    if (t >= 200) return;                       // 200 float4 = 800 channels
    float4 sum = make_float4(0.f, 0.f, 0.f, 0.f);
    float4 mx  = make_float4(0.f, 0.f, 0.f, 0.f);
    float ws = 0.f;
    for (int n = s; n < e2; n++) {
        float w = fw[n];
        ws += w;
        float4 v = ((const float4*)(d_g2 + (size_t)n * HCc))[t];
        sum.x += v.x * w; sum.y += v.y * w; sum.z += v.z * w; sum.w += v.w * w;
        mx.x = fmaxf(mx.x, v.x); mx.y = fmaxf(mx.y, v.y);
        mx.z = fmaxf(mx.z, v.z); mx.w = fmaxf(mx.w, v.w);
    }
    ws = fmaxf(ws, 1e-6f);
    float rws = 1.f / ws;
    float4 mn; mn.x = sum.x * rws; mn.y = sum.y * rws; mn.z = sum.z * rws; mn.w = sum.w * rws;
    ((float4*)(d_pool + g * 2 * HCc))[t] = mn;
    ((float4*)(d_pool + g * 2 * HCc + HCc))[t] = mx;
}

// ---------------- MLP head ----------------
__global__ void __launch_bounds__(128)
k_head(const float* __restrict__ W_fc, const float* __restrict__ b_fc,
       const float* __restrict__ W_out, const float* __restrict__ b_out,
       float* __restrict__ out)
{
    __shared__ float sp[2 * HCc];
    __shared__ float shid[H2c];
    int g = blockIdx.x, t = threadIdx.x;
    for (int k = t; k < 2 * HCc; k += 128) sp[k] = d_pool[g * 2 * HCc + k];
    __syncthreads();
    float acc = b_fc[t];
    for (int k = 0; k < 2 * HCc; k++) acc += sp[k] * W_fc[k * H2c + t];
    shid[t] = fmaxf(acc, 0.f);
    __syncthreads();
    if (t < OUTc) {
        float o = b_out[t];
        #pragma unroll
        for (int k = 0; k < H2c; k++) o += shid[k] * W_out[k * OUTc + t];
        out[g * OUTc + t] = fmaxf(o, 0.f);
    }
}

// ---------------- launch ----------------
extern "C" void kernel_launch(void* const* d_in, const int* in_sizes, int n_in,
                              void* d_out, int out_size)
{
    const float* x     = (const float*)d_in[0];
    const float* pe    = (const float*)d_in[1];
    const int*   ei    = (const int*)  d_in[2];
    const int*   batch = (const int*)  d_in[3];
    const float* fw    = (const float*)d_in[4];
    int wbase = (in_sizes[5] == 1) ? 6 : 5;
    const float* W_pre    = (const float*)d_in[wbase + 0];
    const float* b_pre    = (const float*)d_in[wbase + 1];
    const float* W_l      = (const float*)d_in[wbase + 2];
    const float* b_l      = (const float*)d_in[wbase + 3];
    const float* W_r      = (const float*)d_in[wbase + 4];
    const float* b_r      = (const float*)d_in[wbase + 5];
    const float* att      = (const float*)d_in[wbase + 6];
    const float* gat_bias = (const float*)d_in[wbase + 7];
    const float* W_gcn    = (const float*)d_in[wbase + 8];
    const float* b_gcn    = (const float*)d_in[wbase + 9];
    const float* W_fc     = (const float*)d_in[wbase + 10];
    const float* b_fc     = (const float*)d_in[wbase + 11];
    const float* W_out    = (const float*)d_in[wbase + 12];
    const float* b_out    = (const float*)d_in[wbase + 13];
    float* out = (float*)d_out;

    float* p_h  = nullptr; cudaGetSymbolAddress((void**)&p_h,  d_h);
    float* p_xl = nullptr; cudaGetSymbolAddress((void**)&p_xl, d_xl);
    float* p_xr = nullptr; cudaGetSymbolAddress((void**)&p_xr, d_xr);
    float* p_g1 = nullptr; cudaGetSymbolAddress((void**)&p_g1, d_g1);
    float* p_hg = nullptr; cudaGetSymbolAddress((void**)&p_hg, d_hg);

    // 1: pre-FC GEMM
    {
        dim3 grid((H1c + 127) / 128, (NN + 127) / 128);
        k_gemm_tf32<<<grid, 128>>>(x, W_pre, b_pre, p_h, NN, H1c, FF, FF, H1c, DDc, 1);
    }
    // 2: pe copy
    k_pe<<<(NN * PEc + 255) / 256, 256>>>(pe);
    // 3,4: x_l / x_r projections (slot 4 gets profiled by ncu)
    {
        dim3 grid((HCc + 127) / 128, (NN + 127) / 128);
        k_gemm_tf32<<<grid, 128>>>(p_h, W_l, b_l, p_xl, NN, HCc, DDc, DDc, HCc, HCc, 0);
        k_gemm_tf32<<<grid, 128>>>(p_h, W_r, b_r, p_xr, NN, HCc, DDc, DDc, HCc, HCc, 0);
    }
    // 5-8: CSR build
    k_zero_cnt<<<(NN + 255) / 256, 256>>>();
    k_count<<<(ETOT + 255) / 256, 256>>>(ei);
    k_scan<<<1, 1024>>>();
    k_fill<<<(ETOT + 255) / 256, 256>>>(ei);
    // 9: fused GATv2
    k_gat_fused<<<(NN * 32 + 127) / 128, 128>>>(att, gat_bias);
    // 10: GCN GEMM
    {
        dim3 grid((HCc + 127) / 128, (NN + 127) / 128);
        k_gemm_tf32<<<grid, 128>>>(p_g1, W_gcn, nullptr, p_hg, NN, HCc, HCc, HCc, HCc, HCc, 0);
    }
    // 11: GCN aggregation
    k_gcn_agg<<<(NN * 32 + 255) / 256, 256>>>(b_gcn);
    // 12-14: pooling + head
    k_gstart<<<1, 128>>>(batch);
    k_pool<<<GG, 256>>>(fw);
    k_head<<<GG, 128>>>(W_fc, b_fc, W_out, b_out, out);
}